// round 5
// baseline (speedup 1.0000x reference)
#include <cuda_runtime.h>
#include <math.h>
#include <cstdint>

#define N_TOK 1024
#define TOPK  2
#define NEXP  16
#define HID   1024
#define DIM   2048
#define RNK   16
#define NKTOT (N_TOK*TOPK)
#define LSCALE 0.25f

// ---------------- scratch (static device globals; no allocation) ----------------
__device__ int   g_cnt[NEXP];
__device__ int   g_list[NEXP*NKTOT];
__device__ __align__(16) float g_t[NKTOT*RNK];
__device__ __align__(16) float g_t2[NKTOT*RNK];
__device__ __align__(16) float g_act[(size_t)NKTOT*HID];
__device__ __align__(16) float g_down[(size_t)NKTOT*DIM];

// ---------------- helpers ----------------
__device__ __forceinline__ uint32_t smem_u32(const void* p){
    uint32_t a;
    asm("{ .reg .u64 t; cvta.to.shared.u64 t, %1; cvt.u32.u64 %0, t; }":"=r"(a):"l"(p));
    return a;
}
__device__ __forceinline__ float totf(float x){
    uint32_t u; asm("cvt.rna.tf32.f32 %0, %1;" : "=r"(u) : "f"(x));
    return __uint_as_float(u);
}
__device__ __forceinline__ float4 cv4(float4 v){
    return make_float4(totf(v.x), totf(v.y), totf(v.z), totf(v.w));
}
__device__ __forceinline__ void mma8(float* c, const uint32_t* a, const uint32_t* b){
    asm volatile("mma.sync.aligned.m16n8k8.row.col.f32.tf32.tf32.f32 "
        "{%0,%1,%2,%3}, {%4,%5,%6,%7}, {%8,%9}, {%0,%1,%2,%3};"
        : "+f"(c[0]), "+f"(c[1]), "+f"(c[2]), "+f"(c[3])
        : "r"(a[0]), "r"(a[1]), "r"(a[2]), "r"(a[3]), "r"(b[0]), "r"(b[1]));
}
__device__ __forceinline__ void ldsm4(uint32_t* r, uint32_t addr){
    asm volatile("ldmatrix.sync.aligned.m8n8.x4.shared.b16 {%0,%1,%2,%3}, [%4];"
        : "=r"(r[0]), "=r"(r[1]), "=r"(r[2]), "=r"(r[3]) : "r"(addr));
}
__device__ __forceinline__ float gelu_e(float u){
    return 0.5f*u*(1.0f + erff(u*0.7071067811865476f));
}

// smem layout (dynamic): A 2x16K, B 2x16K, LoRA-B 8K, t 8K, lists
#define ASTG 16384u
#define A_OFF 0u
#define B_OFF 32768u
#define LB_OFF 65536u
#define T_OFF 73728u
#define LS_OFF 81920u
#define TW_OFF 82432u
#define SMEM_BYTES 83968

// ---------------- routing ----------------
__global__ void k_zero() { if (threadIdx.x < NEXP) g_cnt[threadIdx.x] = 0; }

__global__ void k_route(const int* __restrict__ ids) {
    int nk = blockIdx.x*blockDim.x + threadIdx.x;
    if (nk < NKTOT) {
        int e = ids[nk];
        int p = atomicAdd(&g_cnt[e], 1);
        g_list[e*NKTOT + p] = nk;
    }
}

// ---------------- LoRA t vectors ----------------
__global__ void k_t_up(const float* __restrict__ x, const int* __restrict__ ids,
                       const float* __restrict__ up_a) {
    int nk = blockIdx.x;
    int n  = nk / TOPK;
    int e  = ids[nk];
    int warp = threadIdx.x >> 5, lane = threadIdx.x & 31;
    const float4* xr = (const float4*)(x + (size_t)n*DIM);
    const float4* A  = (const float4*)(up_a + (size_t)e*RNK*DIM);
    #pragma unroll
    for (int rr = 0; rr < 4; rr++) {
        int r = warp*4 + rr;
        const float4* ar = A + (size_t)r*(DIM/4);
        float s = 0.f;
        for (int i = lane; i < DIM/4; i += 32) {
            float4 xv = xr[i], av = ar[i];
            s += xv.x*av.x + xv.y*av.y + xv.z*av.z + xv.w*av.w;
        }
        #pragma unroll
        for (int o = 16; o > 0; o >>= 1) s += __shfl_xor_sync(0xffffffffu, s, o);
        if (lane == 0) g_t[nk*RNK + r] = s;
    }
}

__global__ void k_t_down(const int* __restrict__ ids, const float* __restrict__ down_a) {
    int nk = blockIdx.x;
    int e  = ids[nk];
    int warp = threadIdx.x >> 5, lane = threadIdx.x & 31;
    const float4* xr = (const float4*)(g_act + (size_t)nk*HID);
    const float4* A  = (const float4*)(down_a + (size_t)e*RNK*HID);
    #pragma unroll
    for (int rr = 0; rr < 4; rr++) {
        int r = warp*4 + rr;
        const float4* ar = A + (size_t)r*(HID/4);
        float s = 0.f;
        for (int i = lane; i < HID/4; i += 32) {
            float4 xv = xr[i], av = ar[i];
            s += xv.x*av.x + xv.y*av.y + xv.z*av.z + xv.w*av.w;
        }
        #pragma unroll
        for (int o = 16; o > 0; o >>= 1) s += __shfl_xor_sync(0xffffffffu, s, o);
        if (lane == 0) g_t2[nk*RNK + r] = s;
    }
}

// ---------------- up GEMM: 128x128 tile, u1/u2 interleaved, direct epilogue ----------------
__global__ __launch_bounds__(256, 1)
void k_up_tc(const float* __restrict__ x, const float* __restrict__ w_up,
             const float* __restrict__ up_b) {
    int e = blockIdx.z, cnt = g_cnt[e];
    int m0 = blockIdx.y * 128;
    if (m0 >= cnt) return;
    int j0 = blockIdx.x * 64;           // 64 output pairs per CTA

    extern __shared__ __align__(16) char sm[];
    uint32_t sbase = smem_u32(sm);
    int tid = threadIdx.x, wid = tid >> 5, lid = tid & 31;

    int* ls = (int*)(sm + LS_OFF);
    if (tid < 128) {
        int m = m0 + tid;
        ls[tid] = g_list[e*NKTOT + ((m < cnt) ? m : 0)];
    }
    __syncthreads();

    float* tsm = (float*)(sm + T_OFF);
    float* lb  = (float*)(sm + LB_OFF);
    {
        const float* Bup = up_b + (size_t)e*(2*HID)*RNK;
        #pragma unroll
        for (int q = 0; q < 2; q++) {
            int f = tid*2 + q;          // 0..511 float4
            int row = f >> 2, r4 = f & 3;
            ((float4*)tsm)[f] = ((const float4*)(g_t + (size_t)ls[row]*RNK))[r4];
            int grow = (row & 1) ? (HID + j0 + (row >> 1)) : (j0 + (row >> 1));
            ((float4*)lb)[f] = ((const float4*)(Bup + (size_t)grow*RNK))[r4];
        }
    }

    // producers: 128 rows x 32 floats per tile, 2 threads/row
    int a_row = tid >> 1, a_seg = tid & 1;
    const float* ap = x + (size_t)(ls[a_row] >> 1)*DIM + a_seg*16;
    const float* W  = w_up + (size_t)e*(2*HID)*(size_t)DIM;
    int bgrow = (a_row & 1) ? (HID + j0 + (a_row >> 1)) : (j0 + (a_row >> 1));
    const float* bp = W + (size_t)bgrow*DIM + a_seg*16;

    float4 va[4], vb[4];
    #pragma unroll
    for (int q = 0; q < 4; q++) { va[q] = ((const float4*)ap)[q]; vb[q] = ((const float4*)bp)[q]; }
    {
        float* As = (float*)(sm + A_OFF);
        float* Bs = (float*)(sm + B_OFF);
        #pragma unroll
        for (int q = 0; q < 4; q++) {
            ((float4*)As)[(a_row<<3) + ((a_seg*4 + q) ^ (a_row & 7))] = cv4(va[q]);
            ((float4*)Bs)[(a_row<<3) + ((a_seg*4 + q) ^ (a_row & 7))] = cv4(vb[q]);
        }
    }
    __syncthreads();

    // consumer geometry: 8 warps 4x2, warp tile 32(m) x 64(n)
    int warp_m = wid & 3, warp_n = wid >> 2;
    int rsub = lid & 7, mat_lo = (lid >> 3) & 1, mat_hi = (lid >> 4) & 1;
    uint32_t offA[2], offB[4], xqa[4], xqb[4];
    {
        int ar = warp_m*32 + mat_lo*8 + rsub;
        int br = warp_n*64 + mat_hi*8 + rsub;
        #pragma unroll
        for (int mi = 0; mi < 2; mi++) offA[mi] = (uint32_t)((ar + mi*16) << 7);
        #pragma unroll
        for (int p = 0; p < 4; p++)    offB[p]  = (uint32_t)((br + p*16) << 7);
        #pragma unroll
        for (int ks = 0; ks < 4; ks++) {
            xqa[ks] = (uint32_t)((((2*ks + mat_hi) ^ rsub) & 7) << 4);
            xqb[ks] = (uint32_t)((((2*ks + mat_lo) ^ rsub) & 7) << 4);
        }
    }

    float acc[2][8][4];
    #pragma unroll
    for (int mi = 0; mi < 2; mi++)
        #pragma unroll
        for (int ni = 0; ni < 8; ni++)
            #pragma unroll
            for (int q = 0; q < 4; q++) acc[mi][ni][q] = 0.f;

    const int NC = DIM/32;
    for (int c = 0; c < NC; c++) {
        int s = c & 1;
        if (c + 1 < NC) {
            #pragma unroll
            for (int q = 0; q < 4; q++) {
                va[q] = ((const float4*)(ap + (c+1)*32))[q];
                vb[q] = ((const float4*)(bp + (c+1)*32))[q];
            }
        }
        uint32_t AbS = sbase + A_OFF + s*ASTG;
        uint32_t BbS = sbase + B_OFF + s*ASTG;
        #pragma unroll
        for (int ks = 0; ks < 4; ks++) {
            uint32_t af[2][4], bf[8][2];
            #pragma unroll
            for (int mi = 0; mi < 2; mi++)
                ldsm4(af[mi], AbS + offA[mi] + xqa[ks]);
            #pragma unroll
            for (int p = 0; p < 4; p++) {
                uint32_t t4[4];
                ldsm4(t4, BbS + offB[p] + xqb[ks]);
                bf[2*p][0]   = t4[0]; bf[2*p][1]   = t4[1];
                bf[2*p+1][0] = t4[2]; bf[2*p+1][1] = t4[3];
            }
            #pragma unroll
            for (int mi = 0; mi < 2; mi++)
                #pragma unroll
                for (int ni = 0; ni < 8; ni++)
                    mma8(acc[mi][ni], af[mi], bf[ni]);
        }
        __syncthreads();
        if (c + 1 < NC) {
            float* Aw = (float*)(sm + A_OFF + (s^1)*ASTG);
            float* Bw = (float*)(sm + B_OFF + (s^1)*ASTG);
            #pragma unroll
            for (int q = 0; q < 4; q++) {
                ((float4*)Aw)[(a_row<<3) + ((a_seg*4 + q) ^ (a_row & 7))] = cv4(va[q]);
                ((float4*)Bw)[(a_row<<3) + ((a_seg*4 + q) ^ (a_row & 7))] = cv4(vb[q]);
            }
        }
        __syncthreads();
    }

    // direct epilogue: quad cols (2t, 2t+1) = (u1, u2) of pair p = wn*32+ni*4+t
    int g = lid >> 2, t = lid & 3;
    #pragma unroll
    for (int mi = 0; mi < 2; mi++) {
        int r0 = warp_m*32 + mi*16 + g;
        int r1 = r0 + 8;
        float tr0[16], tr1[16];
        #pragma unroll
        for (int q4 = 0; q4 < 4; q4++) {
            ((float4*)tr0)[q4] = ((const float4*)tsm)[r0*4 + q4];
            ((float4*)tr1)[q4] = ((const float4*)tsm)[r1*4 + q4];
        }
        bool v0 = (m0 + r0 < cnt), v1 = (m0 + r1 < cnt);
        float* o0 = g_act + (size_t)ls[r0]*HID + j0;
        float* o1 = g_act + (size_t)ls[r1]*HID + j0;
        #pragma unroll
        for (int ni = 0; ni < 8; ni++) {
            int ccl = warp_n*64 + ni*8 + 2*t;     // tile row of u1 in lb
            int p   = ccl >> 1;                    // pair index 0..63
            float l00 = 0.f, l01 = 0.f, l10 = 0.f, l11 = 0.f;
            #pragma unroll
            for (int r = 0; r < 16; r++) {
                float b0 = lb[ccl*16 + r], b1 = lb[(ccl+1)*16 + r];
                l00 += tr0[r]*b0; l01 += tr0[r]*b1;
                l10 += tr1[r]*b0; l11 += tr1[r]*b1;
            }
            float u1a = acc[mi][ni][0] + LSCALE*l00;
            float u2a = acc[mi][ni][1] + LSCALE*l01;
            float u1b = acc[mi][ni][2] + LSCALE*l10;
            float u2b = acc[mi][ni][3] + LSCALE*l11;
            if (v0) o0[p] = gelu_e(u1a)*u2a;
            if (v1) o1[p] = gelu_e(u1b)*u2b;
        }
    }
}

// ---------------- down GEMM: 128x128 tile, direct epilogue ----------------
__global__ __launch_bounds__(256, 1)
void k_down_tc(const float* __restrict__ tw, const float* __restrict__ w_down,
               const float* __restrict__ down_b) {
    int e = blockIdx.z, cnt = g_cnt[e];
    int m0 = blockIdx.y * 128;
    if (m0 >= cnt) return;
    int d0 = blockIdx.x * 128;

    extern __shared__ __align__(16) char sm[];
    uint32_t sbase = smem_u32(sm);
    int tid = threadIdx.x, wid = tid >> 5, lid = tid & 31;

    int* ls = (int*)(sm + LS_OFF);
    float* twsm = (float*)(sm + TW_OFF);
    if (tid < 128) {
        int m = m0 + tid;
        int nk = g_list[e*NKTOT + ((m < cnt) ? m : 0)];
        ls[tid] = nk;
        twsm[tid] = tw[nk];
    }
    __syncthreads();

    float* tsm = (float*)(sm + T_OFF);
    float* lb  = (float*)(sm + LB_OFF);
    {
        const float* Bdn = down_b + (size_t)e*DIM*RNK;
        #pragma unroll
        for (int q = 0; q < 2; q++) {
            int f = tid*2 + q;
            int row = f >> 2, r4 = f & 3;
            ((float4*)tsm)[f] = ((const float4*)(g_t2 + (size_t)ls[row]*RNK))[r4];
            ((float4*)lb)[f]  = ((const float4*)(Bdn + (size_t)(d0 + row)*RNK))[r4];
        }
    }

    int a_row = tid >> 1, a_seg = tid & 1;
    const float* ap = g_act + (size_t)ls[a_row]*HID + a_seg*16;
    const float* W  = w_down + (size_t)e*DIM*(size_t)HID;
    const float* bp = W + (size_t)(d0 + a_row)*HID + a_seg*16;

    float4 va[4], vb[4];
    #pragma unroll
    for (int q = 0; q < 4; q++) { va[q] = ((const float4*)ap)[q]; vb[q] = ((const float4*)bp)[q]; }
    {
        float* As = (float*)(sm + A_OFF);
        float* Bs = (float*)(sm + B_OFF);
        #pragma unroll
        for (int q = 0; q < 4; q++) {
            ((float4*)As)[(a_row<<3) + ((a_seg*4 + q) ^ (a_row & 7))] = cv4(va[q]);
            ((float4*)Bs)[(a_row<<3) + ((a_seg*4 + q) ^ (a_row & 7))] = cv4(vb[q]);
        }
    }
    __syncthreads();

    int warp_m = wid & 3, warp_n = wid >> 2;
    int rsub = lid & 7, mat_lo = (lid >> 3) & 1, mat_hi = (lid >> 4) & 1;
    uint32_t offA[2], offB[4], xqa[4], xqb[4];
    {
        int ar = warp_m*32 + mat_lo*8 + rsub;
        int br = warp_n*64 + mat_hi*8 + rsub;
        #pragma unroll
        for (int mi = 0; mi < 2; mi++) offA[mi] = (uint32_t)((ar + mi*16) << 7);
        #pragma unroll
        for (int p = 0; p < 4; p++)    offB[p]  = (uint32_t)((br + p*16) << 7);
        #pragma unroll
        for (int ks = 0; ks < 4; ks++) {
            xqa[ks] = (uint32_t)((((2*ks + mat_hi) ^ rsub) & 7) << 4);
            xqb[ks] = (uint32_t)((((2*ks + mat_lo) ^ rsub) & 7) << 4);
        }
    }

    float acc[2][8][4];
    #pragma unroll
    for (int mi = 0; mi < 2; mi++)
        #pragma unroll
        for (int ni = 0; ni < 8; ni++)
            #pragma unroll
            for (int q = 0; q < 4; q++) acc[mi][ni][q] = 0.f;

    const int NC = HID/32;
    for (int c = 0; c < NC; c++) {
        int s = c & 1;
        if (c + 1 < NC) {
            #pragma unroll
            for (int q = 0; q < 4; q++) {
                va[q] = ((const float4*)(ap + (c+1)*32))[q];
                vb[q] = ((const float4*)(bp + (c+1)*32))[q];
            }
        }
        uint32_t AbS = sbase + A_OFF + s*ASTG;
        uint32_t BbS = sbase + B_OFF + s*ASTG;
        #pragma unroll
        for (int ks = 0; ks < 4; ks++) {
            uint32_t af[2][4], bf[8][2];
            #pragma unroll
            for (int mi = 0; mi < 2; mi++)
                ldsm4(af[mi], AbS + offA[mi] + xqa[ks]);
            #pragma unroll
            for (int p = 0; p < 4; p++) {
                uint32_t t4[4];
                ldsm4(t4, BbS + offB[p] + xqb[ks]);
                bf[2*p][0]   = t4[0]; bf[2*p][1]   = t4[1];
                bf[2*p+1][0] = t4[2]; bf[2*p+1][1] = t4[3];
            }
            #pragma unroll
            for (int mi = 0; mi < 2; mi++)
                #pragma unroll
                for (int ni = 0; ni < 8; ni++)
                    mma8(acc[mi][ni], af[mi], bf[ni]);
        }
        __syncthreads();
        if (c + 1 < NC) {
            float* Aw = (float*)(sm + A_OFF + (s^1)*ASTG);
            float* Bw = (float*)(sm + B_OFF + (s^1)*ASTG);
            #pragma unroll
            for (int q = 0; q < 4; q++) {
                ((float4*)Aw)[(a_row<<3) + ((a_seg*4 + q) ^ (a_row & 7))] = cv4(va[q]);
                ((float4*)Bw)[(a_row<<3) + ((a_seg*4 + q) ^ (a_row & 7))] = cv4(vb[q]);
            }
        }
        __syncthreads();
    }

    // direct epilogue: float2 stores
    int g = lid >> 2, t = lid & 3;
    #pragma unroll
    for (int mi = 0; mi < 2; mi++) {
        int r0 = warp_m*32 + mi*16 + g;
        int r1 = r0 + 8;
        float tr0[16], tr1[16];
        #pragma unroll
        for (int q4 = 0; q4 < 4; q4++) {
            ((float4*)tr0)[q4] = ((const float4*)tsm)[r0*4 + q4];
            ((float4*)tr1)[q4] = ((const float4*)tsm)[r1*4 + q4];
        }
        bool v0 = (m0 + r0 < cnt), v1 = (m0 + r1 < cnt);
        float tw0 = twsm[r0], tw1 = twsm[r1];
        float* o0 = g_down + (size_t)ls[r0]*DIM + d0;
        float* o1 = g_down + (size_t)ls[r1]*DIM + d0;
        #pragma unroll
        for (int ni = 0; ni < 8; ni++) {
            int cc = warp_n*64 + ni*8 + 2*t;
            float l00 = 0.f, l01 = 0.f, l10 = 0.f, l11 = 0.f;
            #pragma unroll
            for (int r = 0; r < 16; r++) {
                float b0 = lb[cc*16 + r], b1 = lb[(cc+1)*16 + r];
                l00 += tr0[r]*b0; l01 += tr0[r]*b1;
                l10 += tr1[r]*b0; l11 += tr1[r]*b1;
            }
            if (v0) *(float2*)(o0 + cc) = make_float2(
                (acc[mi][ni][0] + LSCALE*l00)*tw0, (acc[mi][ni][1] + LSCALE*l01)*tw0);
            if (v1) *(float2*)(o1 + cc) = make_float2(
                (acc[mi][ni][2] + LSCALE*l10)*tw1, (acc[mi][ni][3] + LSCALE*l11)*tw1);
        }
    }
}

// ---------------- deterministic k-sum ----------------
__global__ void k_combine(float* __restrict__ out) {
    int idx = blockIdx.x*blockDim.x + threadIdx.x;
    if (idx < N_TOK*DIM/4) {
        int n    = idx / (DIM/4);
        int rest = idx - n*(DIM/4);
        const float4* a = (const float4*)g_down + (size_t)(2*n)*(DIM/4) + rest;
        const float4* b = a + (DIM/4);
        float4 va = *a, vb = *b;
        ((float4*)out)[idx] = make_float4(va.x+vb.x, va.y+vb.y, va.z+vb.z, va.w+vb.w);
    }
}

// ---------------- launch ----------------
extern "C" void kernel_launch(void* const* d_in, const int* in_sizes, int n_in,
                              void* d_out, int out_size) {
    const float* x      = (const float*)d_in[0];
    const float* tw     = (const float*)d_in[1];
    const int*   ids    = (const int*)  d_in[2];
    const float* w_up   = (const float*)d_in[3];
    const float* w_down = (const float*)d_in[4];
    const float* up_a   = (const float*)d_in[5];
    const float* up_b   = (const float*)d_in[6];
    const float* down_a = (const float*)d_in[7];
    const float* down_b = (const float*)d_in[8];
    float* out = (float*)d_out;
    (void)in_sizes; (void)n_in; (void)out_size;

    cudaFuncSetAttribute(k_up_tc,   cudaFuncAttributeMaxDynamicSharedMemorySize, SMEM_BYTES);
    cudaFuncSetAttribute(k_down_tc, cudaFuncAttributeMaxDynamicSharedMemorySize, SMEM_BYTES);

    k_zero<<<1, 32>>>();
    k_route<<<(NKTOT+255)/256, 256>>>(ids);
    k_t_up<<<NKTOT, 128>>>(x, ids, up_a);
    k_up_tc<<<dim3(HID/64, NKTOT/128, NEXP), 256, SMEM_BYTES>>>(x, w_up, up_b);
    k_t_down<<<NKTOT, 128>>>(ids, down_a);
    k_down_tc<<<dim3(DIM/128, NKTOT/128, NEXP), 256, SMEM_BYTES>>>(tw, w_down, down_b);
    k_combine<<<(N_TOK*DIM/4 + 255)/256, 256>>>(out);
}